// round 2
// baseline (speedup 1.0000x reference)
#include <cuda_runtime.h>

// Quantized SH encoding, degree 4.
// fpq(v) with (int_bits=6, frac_bits=10): round-half-even to 1/1024 grid,
// clamp to [-64, 64 - 1/1024]. FEAT_BITS == RES_BITS so one fpq serves all.

__device__ __forceinline__ float fpq(float v) {
    // rintf = round-half-to-even, matches jnp.round
    float q = __fmul_rn(rintf(__fmul_rn(v, 1024.0f)), 0.0009765625f); // /1024
    q = fmaxf(q, -64.0f);
    q = fminf(q, 63.9990234375f);
    return q;
}

__global__ void __launch_bounds__(256) qsh_kernel(const float* __restrict__ in,
                                                  float4* __restrict__ out,
                                                  int n) {
    int i = blockIdx.x * blockDim.x + threadIdx.x;
    if (i >= n) return;

    const float vx = in[3 * i + 0];
    const float vy = in[3 * i + 1];
    const float vz = in[3 * i + 2];

    // x = fpq(in*2 - 1): mul then sub, no fma (match jax op sequence)
    const float x = fpq(__fadd_rn(__fmul_rn(vx, 2.0f), -1.0f));
    const float y = fpq(__fadd_rn(__fmul_rn(vy, 2.0f), -1.0f));
    const float z = fpq(__fadd_rn(__fmul_rn(vz, 2.0f), -1.0f));

    const float xy = fpq(__fmul_rn(x, y));
    const float xz = fpq(__fmul_rn(x, z));
    const float yz = fpq(__fmul_rn(y, z));
    const float x2 = fpq(__fmul_rn(x, x));
    const float y2 = fpq(__fmul_rn(y, y));
    const float z2 = fpq(__fmul_rn(z, z));

    // quantized SH coefficients (qc == fpq on the constant; compiler folds)
    const float C0  = fpq(0.28209479177387814f);
    const float C1  = fpq(-0.48860251190291987f);
    const float C1p = fpq(0.48860251190291987f);
    const float C2a = fpq(1.0925484305920792f);
    const float C2b = fpq(-1.0925484305920792f);
    const float C2c = fpq(0.94617469575756f);
    const float C2d = fpq(0.31539156525252f);
    const float C2e = fpq(0.5462742152960396f);
    const float C3a = fpq(0.5900435899266435f);
    const float C3b = fpq(2.890611442640554f);
    const float C3c = fpq(0.4570457994644657f);
    const float C3d = fpq(0.3731763325901154f);
    const float C3e = fpq(1.445305721320277f);

    float c[16];
    // degree 1
    c[0] = C0;
    // degree 2
    c[1] = fpq(__fmul_rn(C1,  fpq(y)));
    c[2] = fpq(__fmul_rn(C1p, fpq(z)));
    c[3] = fpq(__fmul_rn(C1,  fpq(x)));
    // degree 3
    c[4] = fpq(__fmul_rn(C2a, fpq(xy)));
    c[5] = fpq(__fmul_rn(C2b, fpq(yz)));
    c[6] = fpq(__fsub_rn(__fmul_rn(C2c, fpq(z2)), C2d));
    c[7] = fpq(__fmul_rn(C2b, fpq(xz)));
    c[8] = fpq(__fsub_rn(__fmul_rn(C2e, fpq(x2)), __fmul_rn(C2e, fpq(y2))));
    // degree 4
    {
        float t = fpq(__fadd_rn(__fmul_rn(-3.0f, x2), y2));      // qf(-3*x2 + y2)
        c[9] = fpq(__fmul_rn(__fmul_rn(C3a, fpq(y)), t));
    }
    c[10] = fpq(__fmul_rn(__fmul_rn(C3b, fpq(xy)), fpq(z)));
    {
        float t = fpq(__fadd_rn(1.0f, __fmul_rn(-5.0f, z2)));    // qf(1 - 5*z2)
        c[11] = fpq(__fmul_rn(__fmul_rn(C3c, fpq(y)), t));
        c[13] = fpq(__fmul_rn(__fmul_rn(C3c, fpq(x)), t));
    }
    {
        float t = fpq(__fadd_rn(__fmul_rn(5.0f, z2), -3.0f));    // qf(5*z2 - 3)
        c[12] = fpq(__fmul_rn(__fmul_rn(C3d, fpq(z)), t));
    }
    {
        float t = fpq(__fsub_rn(x2, y2));                        // qf(x2 - y2)
        c[14] = fpq(__fmul_rn(__fmul_rn(C3e, fpq(z)), t));
    }
    {
        float t = fpq(__fadd_rn(__fmul_rn(3.0f, y2), -x2));      // qf(-x2 + 3*y2)
        c[15] = fpq(__fmul_rn(__fmul_rn(C3a, fpq(x)), t));
    }

    float4* o = out + (size_t)i * 4;
    o[0] = make_float4(c[0],  c[1],  c[2],  c[3]);
    o[1] = make_float4(c[4],  c[5],  c[6],  c[7]);
    o[2] = make_float4(c[8],  c[9],  c[10], c[11]);
    o[3] = make_float4(c[12], c[13], c[14], c[15]);
}

extern "C" void kernel_launch(void* const* d_in, const int* in_sizes, int n_in,
                              void* d_out, int out_size) {
    const float* in = (const float*)d_in[0];
    float4* out = (float4*)d_out;
    int n = in_sizes[0] / 3;   // [N,3]
    int threads = 256;
    int blocks = (n + threads - 1) / threads;
    qsh_kernel<<<blocks, threads>>>(in, out, n);
}

// round 5
// speedup vs baseline: 1.1211x; 1.1211x over previous
#include <cuda_runtime.h>

// Quantized SH encoding, degree 4. fpq: round-half-even to 1/1024 grid,
// clamp to [-64, 64 - 1/1024]. FEAT_BITS == RES_BITS so one fpq serves all.
//
// R2: smem-staged coalescing. R1's per-thread float4 stores (64B lane stride)
// inflated L1 store wavefronts 4x (L1=74.7% > DRAM=46.5%). Now:
//   - input staged via coalesced LDG.128, read from smem at stride 3 (conflict-free)
//   - results staged in smem rows of stride 17 (conflict-free STS, <=2-way LDS)
//   - writeback: 16 coalesced STG.32/thread, ideal 1 line per warp-instruction.

__device__ __forceinline__ float fpq(float v) {
    float q = __fmul_rn(rintf(__fmul_rn(v, 1024.0f)), 0.0009765625f); // /1024
    q = fmaxf(q, -64.0f);
    q = fminf(q, 63.9990234375f);
    return q;
}

__global__ void __launch_bounds__(256) qsh_kernel(const float* __restrict__ in,
                                                  float* __restrict__ out,
                                                  int n) {
    __shared__ float s_in[768];          // 256 points * 3
    __shared__ float s_out[256 * 17];    // stride 17 to dodge bank conflicts

    const int t = threadIdx.x;
    const long long blockBase = (long long)blockIdx.x * 256;
    const int remaining = n - (int)blockBase;
    const bool full = remaining >= 256;

    // ---- stage input (coalesced) ----
    if (full) {
        const float4* in4 = (const float4*)(in + blockBase * 3);
        if (t < 192) ((float4*)s_in)[t] = in4[t];
    } else {
        const int cnt = remaining * 3;
        for (int k = t; k < cnt; k += 256) s_in[k] = in[blockBase * 3 + k];
    }
    __syncthreads();

    const bool active = full || (t < remaining);
    if (active) {
        const float vx = s_in[3 * t + 0];
        const float vy = s_in[3 * t + 1];
        const float vz = s_in[3 * t + 2];

        // x = fpq(in*2 - 1): explicit mul/add, no fma (match jax op sequence)
        const float x = fpq(__fadd_rn(__fmul_rn(vx, 2.0f), -1.0f));
        const float y = fpq(__fadd_rn(__fmul_rn(vy, 2.0f), -1.0f));
        const float z = fpq(__fadd_rn(__fmul_rn(vz, 2.0f), -1.0f));

        const float xy = fpq(__fmul_rn(x, y));
        const float xz = fpq(__fmul_rn(x, z));
        const float yz = fpq(__fmul_rn(y, z));
        const float x2 = fpq(__fmul_rn(x, x));
        const float y2 = fpq(__fmul_rn(y, y));
        const float z2 = fpq(__fmul_rn(z, z));

        // quantized SH coefficients (compile-time folded)
        const float C0  = fpq(0.28209479177387814f);
        const float C1  = fpq(-0.48860251190291987f);
        const float C1p = fpq(0.48860251190291987f);
        const float C2a = fpq(1.0925484305920792f);
        const float C2b = fpq(-1.0925484305920792f);
        const float C2c = fpq(0.94617469575756f);
        const float C2d = fpq(0.31539156525252f);
        const float C2e = fpq(0.5462742152960396f);
        const float C3a = fpq(0.5900435899266435f);
        const float C3b = fpq(2.890611442640554f);
        const float C3c = fpq(0.4570457994644657f);
        const float C3d = fpq(0.3731763325901154f);
        const float C3e = fpq(1.445305721320277f);

        float c[16];
        c[0] = C0;
        c[1] = fpq(__fmul_rn(C1,  fpq(y)));
        c[2] = fpq(__fmul_rn(C1p, fpq(z)));
        c[3] = fpq(__fmul_rn(C1,  fpq(x)));
        c[4] = fpq(__fmul_rn(C2a, fpq(xy)));
        c[5] = fpq(__fmul_rn(C2b, fpq(yz)));
        c[6] = fpq(__fsub_rn(__fmul_rn(C2c, fpq(z2)), C2d));
        c[7] = fpq(__fmul_rn(C2b, fpq(xz)));
        c[8] = fpq(__fsub_rn(__fmul_rn(C2e, fpq(x2)), __fmul_rn(C2e, fpq(y2))));
        {
            float u = fpq(__fadd_rn(__fmul_rn(-3.0f, x2), y2));   // qf(-3*x2 + y2)
            c[9] = fpq(__fmul_rn(__fmul_rn(C3a, fpq(y)), u));
        }
        c[10] = fpq(__fmul_rn(__fmul_rn(C3b, fpq(xy)), fpq(z)));
        {
            float u = fpq(__fadd_rn(1.0f, __fmul_rn(-5.0f, z2))); // qf(1 - 5*z2)
            c[11] = fpq(__fmul_rn(__fmul_rn(C3c, fpq(y)), u));
            c[13] = fpq(__fmul_rn(__fmul_rn(C3c, fpq(x)), u));
        }
        {
            float u = fpq(__fadd_rn(__fmul_rn(5.0f, z2), -3.0f)); // qf(5*z2 - 3)
            c[12] = fpq(__fmul_rn(__fmul_rn(C3d, fpq(z)), u));
        }
        {
            float u = fpq(__fsub_rn(x2, y2));                     // qf(x2 - y2)
            c[14] = fpq(__fmul_rn(__fmul_rn(C3e, fpq(z)), u));
        }
        {
            float u = fpq(__fadd_rn(__fmul_rn(3.0f, y2), -x2));   // qf(-x2 + 3*y2)
            c[15] = fpq(__fmul_rn(__fmul_rn(C3a, fpq(x)), u));
        }

        // conflict-free STS: bank = (17*t + j) % 32, 17 coprime to 32
        #pragma unroll
        for (int j = 0; j < 16; j++) s_out[t * 17 + j] = c[j];
    }
    __syncthreads();

    // ---- coalesced writeback: 4096 contiguous floats per full block ----
    float* ob = out + blockBase * 16;
    const int cntf = (full ? 256 : remaining) * 16;
    #pragma unroll
    for (int r = 0; r < 16; r++) {
        const int idx = t + 256 * r;
        if (idx < cntf) {
            const int p = idx >> 4;
            const int j = idx & 15;
            ob[idx] = s_out[p * 17 + j];
        }
    }
}

extern "C" void kernel_launch(void* const* d_in, const int* in_sizes, int n_in,
                              void* d_out, int out_size) {
    const float* in = (const float*)d_in[0];
    float* out = (float*)d_out;
    int n = in_sizes[0] / 3;   // [N,3]
    int threads = 256;
    int blocks = (n + threads - 1) / threads;
    qsh_kernel<<<blocks, threads>>>(in, out, n);
}

// round 6
// speedup vs baseline: 1.3369x; 1.1924x over previous
#include <cuda_runtime.h>

// Quantized SH encoding, degree 4. fpq: round-half-even to 1/1024 grid,
// clamp to [-64, 64 - 1/1024].
//
// R5: kernel was issue-bound (issue=82.4%, alu=55.5%). Cut instructions:
//  - qf() on already-quantized values / on integer-grid linear combos is an
//    exact identity (value = k/1024, rintf(k*1)=k, clamp range never binds
//    since |combos| <= 4) -> removed ~14 fpq calls, bit-exact.
//  - writeback vectorized: results staged as float4 (stride-5 float4 rows,
//    conflict-free STS.128), 4x {LDS.128 + STG.128} coalesced writeback.

__device__ __forceinline__ float fpq(float v) {
    float q = __fmul_rn(rintf(__fmul_rn(v, 1024.0f)), 0.0009765625f); // /1024
    q = fmaxf(q, -64.0f);
    q = fminf(q, 63.9990234375f);
    return q;
}

__global__ void __launch_bounds__(256) qsh_kernel(const float* __restrict__ in,
                                                  float4* __restrict__ out,
                                                  int n) {
    __shared__ float s_in[768];            // 256 points * 3
    __shared__ float4 s_out[256 * 5];      // stride 5 float4s (20 floats)

    const int t = threadIdx.x;
    const long long blockBase = (long long)blockIdx.x * 256;
    const int remaining = n - (int)blockBase;
    const bool full = remaining >= 256;

    // ---- stage input (coalesced LDG.128) ----
    if (full) {
        const float4* in4 = (const float4*)(in + blockBase * 3);
        if (t < 192) ((float4*)s_in)[t] = in4[t];
    } else {
        const int cnt = remaining * 3;
        for (int k = t; k < cnt; k += 256) s_in[k] = in[blockBase * 3 + k];
    }
    __syncthreads();

    if (full || (t < remaining)) {
        const float vx = s_in[3 * t + 0];
        const float vy = s_in[3 * t + 1];
        const float vz = s_in[3 * t + 2];

        // x = fpq(in*2 - 1): explicit mul/add, no fma (match jax op order)
        const float x = fpq(__fadd_rn(__fmul_rn(vx, 2.0f), -1.0f));
        const float y = fpq(__fadd_rn(__fmul_rn(vy, 2.0f), -1.0f));
        const float z = fpq(__fadd_rn(__fmul_rn(vz, 2.0f), -1.0f));

        const float xy = fpq(__fmul_rn(x, y));
        const float xz = fpq(__fmul_rn(x, z));
        const float yz = fpq(__fmul_rn(y, z));
        const float x2 = fpq(__fmul_rn(x, x));
        const float y2 = fpq(__fmul_rn(y, y));
        const float z2 = fpq(__fmul_rn(z, z));

        // quantized SH coefficients (compile-time folded)
        const float C0  = fpq(0.28209479177387814f);
        const float C1  = fpq(-0.48860251190291987f);
        const float C1p = fpq(0.48860251190291987f);
        const float C2a = fpq(1.0925484305920792f);
        const float C2b = fpq(-1.0925484305920792f);
        const float C2c = fpq(0.94617469575756f);
        const float C2d = fpq(0.31539156525252f);
        const float C2e = fpq(0.5462742152960396f);
        const float C3a = fpq(0.5900435899266435f);
        const float C3b = fpq(2.890611442640554f);
        const float C3c = fpq(0.4570457994644657f);
        const float C3d = fpq(0.3731763325901154f);
        const float C3e = fpq(1.445305721320277f);

        // qf(already-quantized) == identity; composites below are exact
        // integer-grid combos with |value| <= 4 (clamp never binds).
        const float u9  = __fadd_rn(__fmul_rn(-3.0f, x2), y2);   // qf(-3*x2+y2)
        const float u11 = __fadd_rn(1.0f, __fmul_rn(-5.0f, z2)); // qf(1-5*z2)
        const float u12 = __fadd_rn(__fmul_rn(5.0f, z2), -3.0f); // qf(5*z2-3)
        const float u14 = __fsub_rn(x2, y2);                     // qf(x2-y2)
        const float u15 = __fadd_rn(__fmul_rn(3.0f, y2), -x2);   // qf(-x2+3*y2)

        float4 r0, r1, r2, r3;
        r0.x = C0;
        r0.y = fpq(__fmul_rn(C1,  y));
        r0.z = fpq(__fmul_rn(C1p, z));
        r0.w = fpq(__fmul_rn(C1,  x));
        r1.x = fpq(__fmul_rn(C2a, xy));
        r1.y = fpq(__fmul_rn(C2b, yz));
        r1.z = fpq(__fsub_rn(__fmul_rn(C2c, z2), C2d));
        r1.w = fpq(__fmul_rn(C2b, xz));
        r2.x = fpq(__fsub_rn(__fmul_rn(C2e, x2), __fmul_rn(C2e, y2)));
        r2.y = fpq(__fmul_rn(__fmul_rn(C3a, y), u9));
        r2.z = fpq(__fmul_rn(__fmul_rn(C3b, xy), z));
        r2.w = fpq(__fmul_rn(__fmul_rn(C3c, y), u11));
        r3.x = fpq(__fmul_rn(__fmul_rn(C3d, z), u12));
        r3.y = fpq(__fmul_rn(__fmul_rn(C3c, x), u11));
        r3.z = fpq(__fmul_rn(__fmul_rn(C3e, z), u14));
        r3.w = fpq(__fmul_rn(__fmul_rn(C3a, x), u15));

        // STS.128 x4, stride-5 float4 rows: per 8-lane phase the 16B units
        // hit 8 distinct bank groups (gcd(5,8)=1) -> conflict-free.
        float4* so = s_out + t * 5;
        so[0] = r0; so[1] = r1; so[2] = r2; so[3] = r3;
    }
    __syncthreads();

    // ---- coalesced writeback: 1024 contiguous float4 per full block ----
    float4* ob = out + blockBase * 4;
    if (full) {
        #pragma unroll
        for (int r = 0; r < 4; r++) {
            const int q = t + 256 * r;               // float4 index in block
            ob[q] = s_out[(q >> 2) * 5 + (q & 3)];
        }
    } else {
        const int cntq = remaining * 4;
        for (int q = t; q < cntq; q += 256)
            ob[q] = s_out[(q >> 2) * 5 + (q & 3)];
    }
}

extern "C" void kernel_launch(void* const* d_in, const int* in_sizes, int n_in,
                              void* d_out, int out_size) {
    const float* in = (const float*)d_in[0];
    float4* out = (float4*)d_out;
    int n = in_sizes[0] / 3;   // [N,3]
    int threads = 256;
    int blocks = (n + threads - 1) / threads;
    qsh_kernel<<<blocks, threads>>>(in, out, n);
}